// round 16
// baseline (speedup 1.0000x reference)
#include <cuda_runtime.h>
#include <cuda_fp16.h>
#include <cstdint>

#define BB 2
#define SS 2048
#define DD 1024
#define HH 16
#define DK 64
#define MROWS (BB*SS)
#define NEGV -1000000000.0f

// ---------------- scratch ----------------
__device__ __align__(128) __half g_in16[(size_t)3*MROWS*DD];   // q,k,v fp16
__device__ __align__(128) __half g_a16[(size_t)MROWS*DD];      // ctx fp16
__device__ __align__(128) __half g_w16[(size_t)4*DD*DD];       // Wq,Wk,Wv,Wo fp16
__device__ __align__(128) __half g_qh16[(size_t)BB*HH*SS*DK];
__device__ __align__(128) __half g_kh16[(size_t)BB*HH*SS*DK];
__device__ __align__(128) __half g_vt16[(size_t)BB*HH*DK*SS];
__device__ __align__(128) __half g_p16[(size_t)BB*HH*SS*SS];
__device__ float g_pattn_scratch[(size_t)BB*HH*SS*SS];         // fallback

// ---------------- helpers ----------------
__device__ __forceinline__ uint32_t smem_u32(const void* p) {
    uint32_t a;
    asm("{ .reg .u64 t; cvta.to.shared.u64 t, %1; cvt.u32.u64 %0, t; }" : "=r"(a) : "l"(p));
    return a;
}

#define CP_ASYNC16(dst, src) \
    asm volatile("cp.async.cg.shared.global [%0], [%1], 16;" :: "r"(dst), "l"(src) : "memory")
#define CP_COMMIT() asm volatile("cp.async.commit_group;" ::: "memory")
#define CP_WAIT(n)  asm volatile("cp.async.wait_group %0;" :: "n"(n) : "memory")

__device__ __forceinline__ void ldm_x4(uint32_t addr, uint32_t& r0, uint32_t& r1,
                                       uint32_t& r2, uint32_t& r3) {
    asm volatile("ldmatrix.sync.aligned.m8n8.x4.shared.b16 {%0,%1,%2,%3}, [%4];"
                 : "=r"(r0), "=r"(r1), "=r"(r2), "=r"(r3) : "r"(addr));
}

__device__ __forceinline__ void mma16816(float* c, const uint32_t* a, const uint32_t* b) {
    asm volatile("mma.sync.aligned.m16n8k16.row.col.f32.f16.f16.f32 "
                 "{%0,%1,%2,%3},{%4,%5,%6,%7},{%8,%9},{%0,%1,%2,%3};"
                 : "+f"(c[0]), "+f"(c[1]), "+f"(c[2]), "+f"(c[3])
                 : "r"(a[0]), "r"(a[1]), "r"(a[2]), "r"(a[3]), "r"(b[0]), "r"(b[1]));
}

// (rows x 32 half) tile, 80B padded rows, 256 threads
__device__ __forceinline__ void ld_tile(uint32_t dst, const __half* g, int ldh,
                                        int rows, int tid) {
    for (int ci = tid; ci < rows * 4; ci += 256) {
        int r = ci >> 2, c = ci & 3;
        CP_ASYNC16(dst + (uint32_t)(r * 80 + c * 16), g + (size_t)r * ldh + c * 8);
    }
}

// ============================================================================
// fp16 MMA GEMM, 256 threads / 8 warps, 2 CTAs per SM. Direct reg->gmem
// epilogues everywhere except the V-transpose (MODE7 z==2).
// MODE: 0 proj->fp32 flat +bias | 3 scores masked fp32 | 4 AV ctx half
//       7 merged QKV proj (z=0:q, z=1:k half head layout; z=2: vT via smem)
// ============================================================================
template<int WARPS_M, int WARPS_N, int WMI, int WNI, int S, int MODE>
__global__ __launch_bounds__(256, 2) void tc_mm(
    const __half* __restrict__ A, int lda, size_t aZ,
    const __half* __restrict__ B, int ldb, size_t bZ,
    int K,
    const float* __restrict__ bias,
    const float* __restrict__ bias2,
    const float* __restrict__ bias3,
    const int*   __restrict__ mask,
    float* __restrict__ outF,
    __half* __restrict__ outH,
    __half* __restrict__ outH2,
    __half* __restrict__ outH3)
{
    constexpr int BM  = WARPS_M * WMI * 16;
    constexpr int BN  = WARPS_N * WNI * 8;
    constexpr int BNP = BN + 5;   // odd pad for transpose staging (MODE7 z==2)
    constexpr int ASZ = BM * 80;
    constexpr int BSZ = BN * 80;
    constexpr int STG = ASZ + BSZ;
    constexpr int NJ  = WNI / 2;

    extern __shared__ char smraw[];
    char* sm = (char*)(((uintptr_t)smraw + 127) & ~(uintptr_t)127);
    uint32_t smu = smem_u32(sm);

    const int tid  = threadIdx.x;
    const int w    = tid >> 5, lane = tid & 31;
    const int bn   = blockIdx.x * BN, bm = blockIdx.y * BM;
    const int z    = blockIdx.z;

    A += (size_t)z * aZ + (size_t)bm * lda;
    B += (size_t)z * bZ + (size_t)bn * ldb;

    const int wm = (w / WARPS_N) * (WMI * 16);
    const int wn = (w % WARPS_N) * (WNI * 8);

    float acc[WMI][WNI][4];
#pragma unroll
    for (int mi = 0; mi < WMI; mi++)
#pragma unroll
        for (int nt = 0; nt < WNI; nt++)
#pragma unroll
            for (int x = 0; x < 4; x++) acc[mi][nt][x] = 0.f;

    const int NK = K / 32;
#pragma unroll
    for (int s = 0; s < S - 1; s++) {
        if (s < NK) {
            ld_tile(smu + s * STG,       A + s * 32, lda, BM, tid);
            ld_tile(smu + s * STG + ASZ, B + s * 32, ldb, BN, tid);
        }
        CP_COMMIT();
    }

    const int rA = (lane & 7) + ((lane >> 3) & 1) * 8;
    const int kO = ((lane >> 4) << 3) * 2;

    for (int kt = 0; kt < NK; kt++) {
        CP_WAIT(S - 2);
        __syncthreads();
        uint32_t sA = smu + (kt % S) * STG;
        uint32_t sB = sA + ASZ;
#pragma unroll
        for (int ks = 0; ks < 2; ks++) {
            uint32_t a[WMI][4], bf[WNI][2];
            uint32_t kb = (uint32_t)(ks * 32 + kO);
#pragma unroll
            for (int mi = 0; mi < WMI; mi++)
                ldm_x4(sA + (uint32_t)((wm + mi * 16 + rA) * 80) + kb,
                       a[mi][0], a[mi][1], a[mi][2], a[mi][3]);
#pragma unroll
            for (int nj = 0; nj < NJ; nj++) {
                uint32_t r0, r1, r2, r3;
                ldm_x4(sB + (uint32_t)((wn + nj * 16 + rA) * 80) + kb, r0, r1, r2, r3);
                bf[nj * 2 + 0][0] = r0; bf[nj * 2 + 1][0] = r1;
                bf[nj * 2 + 0][1] = r2; bf[nj * 2 + 1][1] = r3;
            }
#pragma unroll
            for (int mi = 0; mi < WMI; mi++)
#pragma unroll
                for (int nt = 0; nt < WNI; nt++)
                    mma16816(acc[mi][nt], a[mi], bf[nt]);
        }
        int ns = kt + S - 1;
        if (ns < NK) {
            ld_tile(smu + (ns % S) * STG,       A + ns * 32, lda, BM, tid);
            ld_tile(smu + (ns % S) * STG + ASZ, B + ns * 32, ldb, BN, tid);
        }
        CP_COMMIT();
    }
    CP_WAIT(0);
    __syncthreads();

    float* esm = (float*)sm;
    const int er = lane >> 2, ec = (lane & 3) * 2;

    // ---- MODE7 z==2: V projection with coalesced transpose (vT layout) ----
    if (MODE == 7 && z == 2) {
#pragma unroll
        for (int mi = 0; mi < WMI; mi++)
#pragma unroll
            for (int nt = 0; nt < WNI; nt++) {
                int r0 = wm + mi * 16 + er;
                int c0 = wn + nt * 8 + ec;
                esm[(size_t)r0 * BNP + c0]           = acc[mi][nt][0];
                esm[(size_t)r0 * BNP + c0 + 1]       = acc[mi][nt][1];
                esm[(size_t)(r0 + 8) * BNP + c0]     = acc[mi][nt][2];
                esm[(size_t)(r0 + 8) * BNP + c0 + 1] = acc[mi][nt][3];
            }
        __syncthreads();
        const int bb = bm >> 11;
        const int sbase = bm & (SS - 1);
        for (int ci = tid; ci < BN * (BM / 4); ci += 256) {
            int e  = ci >> 5;          // BM/4 == 32
            int mg = ci & 31;
            int eg = bn + e;
            int h = eg >> 6, dk = eg & 63;
            float bv = bias3[eg];
            float v0 = esm[(size_t)(mg * 4 + 0) * BNP + e] + bv;
            float v1 = esm[(size_t)(mg * 4 + 1) * BNP + e] + bv;
            float v2 = esm[(size_t)(mg * 4 + 2) * BNP + e] + bv;
            float v3 = esm[(size_t)(mg * 4 + 3) * BNP + e] + bv;
            __half2* dst = (__half2*)&outH3[((size_t)((bb * HH + h)) * DK + dk) * SS
                                            + sbase + mg * 4];
            dst[0] = __floats2half2_rn(v0, v1);
            dst[1] = __floats2half2_rn(v2, v3);
        }
        return;
    }

    // ---- all other modes: direct register -> global ----
#pragma unroll
    for (int mi = 0; mi < WMI; mi++)
#pragma unroll
        for (int hx = 0; hx < 2; hx++) {
            const int m = bm + wm + mi * 16 + er + hx * 8;   // global row (tile M dim)
            if (MODE == 3) {
                const int bb = z >> 4;
                const int* mp = mask + ((size_t)bb * SS + m) * SS + bn + wn + ec;
                float* pp = outF + (size_t)z * SS * SS + (size_t)m * SS + bn + wn + ec;
#pragma unroll
                for (int nt = 0; nt < WNI; nt++) {
                    int2 mm = *(const int2*)(mp + nt * 8);
                    float2 o;
                    o.x = mm.x ? acc[mi][nt][hx*2+0] * 0.125f : NEGV;
                    o.y = mm.y ? acc[mi][nt][hx*2+1] * 0.125f : NEGV;
                    *(float2*)(pp + nt * 8) = o;
                }
            } else if (MODE == 0) {
                float* pp = outF + (size_t)m * DD + bn + wn + ec;
                const float* bp = bias + bn + wn + ec;
#pragma unroll
                for (int nt = 0; nt < WNI; nt++) {
                    float2 o;
                    o.x = acc[mi][nt][hx*2+0] + bp[nt*8];
                    o.y = acc[mi][nt][hx*2+1] + bp[nt*8+1];
                    *(float2*)(pp + nt * 8) = o;
                }
            } else if (MODE == 7) {  // z==0/1: half head layout (bb,h,s,dk)
                const float* bz = (z == 0) ? bias : bias2;
                __half* dsth = (z == 0) ? outH : outH2;
                const int bb = m >> 11, s = m & (SS - 1);
#pragma unroll
                for (int nt = 0; nt < WNI; nt++) {
                    int e = bn + wn + nt * 8 + ec;
                    int h = e >> 6, dk = e & 63;
                    __half2 o = __floats2half2_rn(acc[mi][nt][hx*2+0] + bz[e],
                                                  acc[mi][nt][hx*2+1] + bz[e+1]);
                    *(__half2*)&dsth[(((size_t)(bb * HH + h)) * SS + s) * DK + dk] = o;
                }
            } else {  // MODE 4: ctx half (b,s,d); m = local q-row, z = b*HH+h
                const int bb = z >> 4, h = z & 15;
                __half* pp = outH + ((size_t)bb * SS + m) * DD + h * DK + bn + wn + ec;
#pragma unroll
                for (int nt = 0; nt < WNI; nt++) {
                    __half2 o = __floats2half2_rn(acc[mi][nt][hx*2+0],
                                                  acc[mi][nt][hx*2+1]);
                    *(__half2*)(pp + nt * 8) = o;
                }
            }
        }
}

// ======================= one merged fp32 -> fp16 convert =======================
__global__ __launch_bounds__(256) void k_f2hall(
    const float* __restrict__ q, const float* __restrict__ k, const float* __restrict__ v,
    const float* __restrict__ w0, const float* __restrict__ w1,
    const float* __restrict__ w2, const float* __restrict__ w3,
    __half* __restrict__ in16, __half* __restrict__ w16, int nW)
{
    int y = blockIdx.y;
    const float* x;
    __half* dst;
    if (y < 3) {
        x = (y == 0) ? q : (y == 1) ? k : v;
        dst = in16 + (size_t)y * MROWS * DD;
    } else {
        if (blockIdx.x >= (unsigned)nW) return;
        x = (y == 3) ? w0 : (y == 4) ? w1 : (y == 5) ? w2 : w3;
        dst = w16 + (size_t)(y - 3) * DD * DD;
    }
    size_t i = ((size_t)blockIdx.x * 256 + threadIdx.x) * 4;
    float4 val = *(const float4*)(x + i);
    *(__half2*)(dst + i)     = __floats2half2_rn(val.x, val.y);
    *(__half2*)(dst + i + 2) = __floats2half2_rn(val.z, val.w);
}

// ======================= warp-per-row softmax =======================
__global__ __launch_bounds__(256, 3) void k_softmax_w(float* __restrict__ P,
                                                      __half* __restrict__ P16)
{
    const size_t row = (size_t)blockIdx.x * 8 + (threadIdx.x >> 5);
    const int lane = threadIdx.x & 31;
    float4* p = (float4*)(P + row * SS);
    __half2* ph = (__half2*)(P16 + row * SS);

    float4 v[16];
#pragma unroll
    for (int i = 0; i < 16; i++) v[i] = p[lane + i * 32];

    float m = -INFINITY;
#pragma unroll
    for (int i = 0; i < 16; i++)
        m = fmaxf(m, fmaxf(fmaxf(v[i].x, v[i].y), fmaxf(v[i].z, v[i].w)));
#pragma unroll
    for (int o = 16; o; o >>= 1) m = fmaxf(m, __shfl_xor_sync(~0u, m, o));

    float s = 0.f;
#pragma unroll
    for (int i = 0; i < 16; i++) {
        v[i].x = __expf(v[i].x - m);
        v[i].y = __expf(v[i].y - m);
        v[i].z = __expf(v[i].z - m);
        v[i].w = __expf(v[i].w - m);
        s += (v[i].x + v[i].y) + (v[i].z + v[i].w);
    }
#pragma unroll
    for (int o = 16; o; o >>= 1) s += __shfl_xor_sync(~0u, s, o);
    float inv = 1.0f / s;

#pragma unroll
    for (int i = 0; i < 16; i++) {
        v[i].x *= inv; v[i].y *= inv; v[i].z *= inv; v[i].w *= inv;
        p[lane + i * 32] = v[i];
        ph[(lane + i * 32) * 2 + 0] = __floats2half2_rn(v[i].x, v[i].y);
        ph[(lane + i * 32) * 2 + 1] = __floats2half2_rn(v[i].z, v[i].w);
    }
}

// ======================= launch =======================
extern "C" void kernel_launch(void* const* d_in, const int* in_sizes, int n_in,
                              void* d_out, int out_size)
{
    const float* q    = (const float*)d_in[0];
    const float* k    = (const float*)d_in[1];
    const float* v    = (const float*)d_in[2];
    const int*   mask = (const int*)  d_in[3];
    const float* Wq   = (const float*)d_in[4];
    const float* bq_  = (const float*)d_in[5];
    const float* Wk   = (const float*)d_in[6];
    const float* bk_  = (const float*)d_in[7];
    const float* Wv   = (const float*)d_in[8];
    const float* bv_  = (const float*)d_in[9];
    const float* Wo   = (const float*)d_in[10];
    const float* bo_  = (const float*)d_in[11];
    float* out = (float*)d_out;

    const long long out_elems = (long long)MROWS * DD;
    const long long p_elems   = (long long)BB * HH * SS * SS;

    float* p_base;
    if ((long long)out_size >= out_elems + p_elems) {
        p_base = out + out_elems;
    } else {
        void* sp = nullptr;
        cudaGetSymbolAddress(&sp, g_pattn_scratch);
        p_base = (float*)sp;
    }

    void *pin16, *pa16, *pw16, *pqh, *pkh, *pvt, *pp16;
    cudaGetSymbolAddress(&pin16, g_in16);
    cudaGetSymbolAddress(&pa16, g_a16);
    cudaGetSymbolAddress(&pw16, g_w16);
    cudaGetSymbolAddress(&pqh,  g_qh16);
    cudaGetSymbolAddress(&pkh,  g_kh16);
    cudaGetSymbolAddress(&pvt,  g_vt16);
    cudaGetSymbolAddress(&pp16, g_p16);
    __half* in16 = (__half*)pin16;
    __half* a16 = (__half*)pa16;
    __half* w16 = (__half*)pw16;
    __half* qh16 = (__half*)pqh;
    __half* kh16 = (__half*)pkh;
    __half* vt16 = (__half*)pvt;
    __half* p16  = (__half*)pp16;

    const size_t inOff = (size_t)MROWS * DD;
    const size_t wOff  = (size_t)DD * DD;

    const int SM_PROJ = 82048;    // max(4*STG=81920, esm 128*133*4=68096) + align
    const int SM_SC   = 61568;    // 3*STG + align
    const int SM_AV   = 102528;   // 4*(256+64)*80 + align
    cudaFuncSetAttribute(tc_mm<2,4,4,4,4,0>, cudaFuncAttributeMaxDynamicSharedMemorySize, SM_PROJ);
    cudaFuncSetAttribute(tc_mm<2,4,4,4,4,7>, cudaFuncAttributeMaxDynamicSharedMemorySize, SM_PROJ);
    cudaFuncSetAttribute(tc_mm<2,4,4,4,3,3>, cudaFuncAttributeMaxDynamicSharedMemorySize, SM_SC);
    cudaFuncSetAttribute(tc_mm<4,2,4,4,4,4>, cudaFuncAttributeMaxDynamicSharedMemorySize, SM_AV);

    const int nIn = MROWS * DD / 1024;
    const int nW  = DD * DD / 1024;

    // all converts in one launch
    k_f2hall<<<dim3(nIn, 7), 256>>>(q, k, v, Wq, Wk, Wv, Wo, in16, w16, nW);

    // merged QKV projections: grid z = 0,1,2
    dim3 gProjQKV(DD / 128, MROWS / 128, 3);
    tc_mm<2,4,4,4,4,7><<<gProjQKV, 256, SM_PROJ>>>(in16, DD, inOff, w16, DD, wOff, DD,
        bq_, bk_, bv_, nullptr, nullptr, qh16, kh16, vt16);

    // scores (raw masked scaled) -> fp32 P, direct reg->gmem epilogue
    dim3 gScores(SS / 128, SS / 128, BB * HH);
    tc_mm<2,4,4,4,3,3><<<gScores, 256, SM_SC>>>(qh16, DK, (size_t)SS * DK,
        kh16, DK, (size_t)SS * DK, DK,
        nullptr, nullptr, nullptr, mask, p_base, nullptr, nullptr, nullptr);

    // warp-per-row softmax + fp16 copy
    k_softmax_w<<<BB * HH * SS / 8, 256>>>(p_base, p16);

    // AV: ctx = P16 @ Vt^T   (BM=256, BN=64, warp tile 64x32)
    dim3 gAV(1, SS / 256, BB * HH);
    tc_mm<4,2,4,4,4,4><<<gAV, 256, SM_AV>>>(p16, SS, (size_t)SS * SS,
        vt16, SS, (size_t)DK * SS, SS,
        nullptr, nullptr, nullptr, nullptr, nullptr, a16, nullptr, nullptr);

    // output projection
    dim3 gProj(DD / 128, MROWS / 128, 1);
    tc_mm<2,4,4,4,4,0><<<gProj, 256, SM_PROJ>>>(a16, DD, 0, w16 + 3 * wOff, DD, 0, DD,
        bo_, nullptr, nullptr, nullptr, out, nullptr, nullptr, nullptr);
}

// round 17
// speedup vs baseline: 1.3672x; 1.3672x over previous
#include <cuda_runtime.h>
#include <cuda_fp16.h>
#include <cstdint>

#define BB 2
#define SS 2048
#define DD 1024
#define HH 16
#define DK 64
#define MROWS (BB*SS)
#define NEGV -1000000000.0f

// ---------------- scratch ----------------
__device__ __align__(128) __half g_in16[(size_t)3*MROWS*DD];   // q,k,v fp16
__device__ __align__(128) __half g_a16[(size_t)MROWS*DD];      // ctx fp16
__device__ __align__(128) __half g_w16[(size_t)4*DD*DD];       // Wq,Wk,Wv,Wo fp16
__device__ __align__(128) __half g_qh16[(size_t)BB*HH*SS*DK];
__device__ __align__(128) __half g_kh16[(size_t)BB*HH*SS*DK];
__device__ __align__(128) __half g_vt16[(size_t)BB*HH*DK*SS];
__device__ __align__(128) __half g_p16[(size_t)BB*HH*SS*SS];
__device__ float g_pattn_scratch[(size_t)BB*HH*SS*SS];         // fallback

// ---------------- helpers ----------------
__device__ __forceinline__ uint32_t smem_u32(const void* p) {
    uint32_t a;
    asm("{ .reg .u64 t; cvta.to.shared.u64 t, %1; cvt.u32.u64 %0, t; }" : "=r"(a) : "l"(p));
    return a;
}

#define CP_ASYNC16(dst, src) \
    asm volatile("cp.async.cg.shared.global [%0], [%1], 16;" :: "r"(dst), "l"(src) : "memory")
#define CP_COMMIT() asm volatile("cp.async.commit_group;" ::: "memory")
#define CP_WAIT(n)  asm volatile("cp.async.wait_group %0;" :: "n"(n) : "memory")

__device__ __forceinline__ void ldm_x4(uint32_t addr, uint32_t& r0, uint32_t& r1,
                                       uint32_t& r2, uint32_t& r3) {
    asm volatile("ldmatrix.sync.aligned.m8n8.x4.shared.b16 {%0,%1,%2,%3}, [%4];"
                 : "=r"(r0), "=r"(r1), "=r"(r2), "=r"(r3) : "r"(addr));
}

__device__ __forceinline__ void mma16816(float* c, const uint32_t* a, const uint32_t* b) {
    asm volatile("mma.sync.aligned.m16n8k16.row.col.f32.f16.f16.f32 "
                 "{%0,%1,%2,%3},{%4,%5,%6,%7},{%8,%9},{%0,%1,%2,%3};"
                 : "+f"(c[0]), "+f"(c[1]), "+f"(c[2]), "+f"(c[3])
                 : "r"(a[0]), "r"(a[1]), "r"(a[2]), "r"(a[3]), "r"(b[0]), "r"(b[1]));
}

// (rows x 32 half) tile, 80B padded rows, 256 threads
__device__ __forceinline__ void ld_tile(uint32_t dst, const __half* g, int ldh,
                                        int rows, int tid) {
    for (int ci = tid; ci < rows * 4; ci += 256) {
        int r = ci >> 2, c = ci & 3;
        CP_ASYNC16(dst + (uint32_t)(r * 80 + c * 16), g + (size_t)r * ldh + c * 8);
    }
}

// ============================================================================
// fp16 MMA GEMM, 256 threads / 8 warps, 2 CTAs per SM.
// MODE: 0 proj->fp32 flat +bias (direct reg->gmem)
//       3 scores masked fp32 (direct reg->gmem)
//       4 AV ctx half (smem staged) | 7 merged QKV proj (smem staged; z=2 vT)
// ============================================================================
template<int WARPS_M, int WARPS_N, int WMI, int WNI, int S, int MODE>
__global__ __launch_bounds__(256, 2) void tc_mm(
    const __half* __restrict__ A, int lda, size_t aZ,
    const __half* __restrict__ B, int ldb, size_t bZ,
    int K,
    const float* __restrict__ bias,
    const float* __restrict__ bias2,
    const float* __restrict__ bias3,
    const int*   __restrict__ mask,
    float* __restrict__ outF,
    __half* __restrict__ outH,
    __half* __restrict__ outH2,
    __half* __restrict__ outH3)
{
    constexpr int BM  = WARPS_M * WMI * 16;
    constexpr int BN  = WARPS_N * WNI * 8;
    constexpr int BNP = BN + 5;   // odd pad for transpose staging (MODE7 z==2)
    constexpr int ASZ = BM * 80;
    constexpr int BSZ = BN * 80;
    constexpr int STG = ASZ + BSZ;
    constexpr int NJ  = WNI / 2;

    extern __shared__ char smraw[];
    char* sm = (char*)(((uintptr_t)smraw + 127) & ~(uintptr_t)127);
    uint32_t smu = smem_u32(sm);

    const int tid  = threadIdx.x;
    const int w    = tid >> 5, lane = tid & 31;
    const int bn   = blockIdx.x * BN, bm = blockIdx.y * BM;
    const int z    = blockIdx.z;

    A += (size_t)z * aZ + (size_t)bm * lda;
    B += (size_t)z * bZ + (size_t)bn * ldb;

    const int wm = (w / WARPS_N) * (WMI * 16);
    const int wn = (w % WARPS_N) * (WNI * 8);

    float acc[WMI][WNI][4];
#pragma unroll
    for (int mi = 0; mi < WMI; mi++)
#pragma unroll
        for (int nt = 0; nt < WNI; nt++)
#pragma unroll
            for (int x = 0; x < 4; x++) acc[mi][nt][x] = 0.f;

    const int NK = K / 32;
#pragma unroll
    for (int s = 0; s < S - 1; s++) {
        if (s < NK) {
            ld_tile(smu + s * STG,       A + s * 32, lda, BM, tid);
            ld_tile(smu + s * STG + ASZ, B + s * 32, ldb, BN, tid);
        }
        CP_COMMIT();
    }

    const int rA = (lane & 7) + ((lane >> 3) & 1) * 8;
    const int kO = ((lane >> 4) << 3) * 2;

    for (int kt = 0; kt < NK; kt++) {
        CP_WAIT(S - 2);
        __syncthreads();
        uint32_t sA = smu + (kt % S) * STG;
        uint32_t sB = sA + ASZ;
#pragma unroll
        for (int ks = 0; ks < 2; ks++) {
            uint32_t a[WMI][4], bf[WNI][2];
            uint32_t kb = (uint32_t)(ks * 32 + kO);
#pragma unroll
            for (int mi = 0; mi < WMI; mi++)
                ldm_x4(sA + (uint32_t)((wm + mi * 16 + rA) * 80) + kb,
                       a[mi][0], a[mi][1], a[mi][2], a[mi][3]);
#pragma unroll
            for (int nj = 0; nj < NJ; nj++) {
                uint32_t r0, r1, r2, r3;
                ldm_x4(sB + (uint32_t)((wn + nj * 16 + rA) * 80) + kb, r0, r1, r2, r3);
                bf[nj * 2 + 0][0] = r0; bf[nj * 2 + 1][0] = r1;
                bf[nj * 2 + 0][1] = r2; bf[nj * 2 + 1][1] = r3;
            }
#pragma unroll
            for (int mi = 0; mi < WMI; mi++)
#pragma unroll
                for (int nt = 0; nt < WNI; nt++)
                    mma16816(acc[mi][nt], a[mi], bf[nt]);
        }
        int ns = kt + S - 1;
        if (ns < NK) {
            ld_tile(smu + (ns % S) * STG,       A + ns * 32, lda, BM, tid);
            ld_tile(smu + (ns % S) * STG + ASZ, B + ns * 32, ldb, BN, tid);
        }
        CP_COMMIT();
    }
    CP_WAIT(0);
    __syncthreads();

    float* esm = (float*)sm;
    const int er = lane >> 2, ec = (lane & 3) * 2;

    // ---- MODE3: scores — direct register->global (sector-complete 8B stores) ----
    if (MODE == 3) {
        const int bb = z >> 4;
        float* Pz = outF + (size_t)z * SS * SS;
#pragma unroll
        for (int mi = 0; mi < WMI; mi++)
#pragma unroll
            for (int hx = 0; hx < 2; hx++) {
                int row = bm + wm + mi * 16 + er + hx * 8;
                const int* mp = mask + ((size_t)bb * SS + row) * SS + bn + wn + ec;
                float* pp = Pz + (size_t)row * SS + bn + wn + ec;
#pragma unroll
                for (int nt = 0; nt < WNI; nt++) {
                    int2 mm = *(const int2*)(mp + nt * 8);
                    float2 o;
                    o.x = mm.x ? acc[mi][nt][hx*2+0] * 0.125f : NEGV;
                    o.y = mm.y ? acc[mi][nt][hx*2+1] * 0.125f : NEGV;
                    *(float2*)(pp + nt * 8) = o;
                }
            }
        return;
    }

    // ---- MODE0: O-projection — direct register->global fp32 +bias ----
    if (MODE == 0) {
#pragma unroll
        for (int mi = 0; mi < WMI; mi++)
#pragma unroll
            for (int hx = 0; hx < 2; hx++) {
                int row = bm + wm + mi * 16 + er + hx * 8;
                float* pp = outF + (size_t)row * DD + bn + wn + ec;
                const float* bp = bias + bn + wn + ec;
#pragma unroll
                for (int nt = 0; nt < WNI; nt++) {
                    float2 o;
                    o.x = acc[mi][nt][hx*2+0] + bp[nt*8];
                    o.y = acc[mi][nt][hx*2+1] + bp[nt*8+1];
                    *(float2*)(pp + nt * 8) = o;
                }
            }
        return;
    }

    // ---- MODE7 z==2: V projection with coalesced transpose (vT layout) ----
    if (MODE == 7 && z == 2) {
#pragma unroll
        for (int mi = 0; mi < WMI; mi++)
#pragma unroll
            for (int nt = 0; nt < WNI; nt++) {
                int r0 = wm + mi * 16 + er;
                int c0 = wn + nt * 8 + ec;
                esm[(size_t)r0 * BNP + c0]           = acc[mi][nt][0];
                esm[(size_t)r0 * BNP + c0 + 1]       = acc[mi][nt][1];
                esm[(size_t)(r0 + 8) * BNP + c0]     = acc[mi][nt][2];
                esm[(size_t)(r0 + 8) * BNP + c0 + 1] = acc[mi][nt][3];
            }
        __syncthreads();
        const int bb = bm >> 11;
        const int sbase = bm & (SS - 1);
        for (int ci = tid; ci < BN * (BM / 4); ci += 256) {
            int e  = ci >> 5;          // BM/4 == 32
            int mg = ci & 31;
            int eg = bn + e;
            int h = eg >> 6, dk = eg & 63;
            float bv = bias3[eg];
            float v0 = esm[(size_t)(mg * 4 + 0) * BNP + e] + bv;
            float v1 = esm[(size_t)(mg * 4 + 1) * BNP + e] + bv;
            float v2 = esm[(size_t)(mg * 4 + 2) * BNP + e] + bv;
            float v3 = esm[(size_t)(mg * 4 + 3) * BNP + e] + bv;
            __half2* dst = (__half2*)&outH3[((size_t)((bb * HH + h)) * DK + dk) * SS
                                            + sbase + mg * 4];
            dst[0] = __floats2half2_rn(v0, v1);
            dst[1] = __floats2half2_rn(v2, v3);
        }
        return;
    }

    // ---- staged epilogue for half-output modes (7 z=0/1, 4) ----
#pragma unroll
    for (int mi = 0; mi < WMI; mi++)
#pragma unroll
        for (int nt = 0; nt < WNI; nt++) {
            int r0 = wm + mi * 16 + er;
            int c0 = wn + nt * 8 + ec;
            *(float2*)&esm[(size_t)r0 * BN + c0]       = make_float2(acc[mi][nt][0], acc[mi][nt][1]);
            *(float2*)&esm[(size_t)(r0 + 8) * BN + c0] = make_float2(acc[mi][nt][2], acc[mi][nt][3]);
        }
    __syncthreads();

    for (int ci = tid; ci < BM * BN / 4; ci += 256) {
        int r  = ci / (BN / 4);
        int c0 = (ci % (BN / 4)) * 4;
        float4 v = *(const float4*)&esm[(size_t)r * BN + c0];
        int m = bm + r;
        if (MODE == 7) {   // z==0 or z==1: head layout (z,s,dk)
            const float* bz = (z == 0) ? bias : bias2;
            __half* dsth = (z == 0) ? outH : outH2;
            int e0 = bn + c0;
            int h = e0 >> 6, dk0 = e0 & 63;
            int bb = m >> 11, s = m & (SS - 1);
            __half2 h0 = __floats2half2_rn(v.x + bz[e0],   v.y + bz[e0+1]);
            __half2 h1 = __floats2half2_rn(v.z + bz[e0+2], v.w + bz[e0+3]);
            __half2* dst = (__half2*)&dsth[(((size_t)(bb * HH + h)) * SS + s) * DK + dk0];
            dst[0] = h0; dst[1] = h1;
        } else { // MODE 4: ctx half (b,s,d); m = local q-row, z = b*HH+h
            int bb = z >> 4, h = z & 15;
            __half2 h0 = __floats2half2_rn(v.x, v.y);
            __half2 h1 = __floats2half2_rn(v.z, v.w);
            __half2* dst = (__half2*)&outH[((size_t)bb * SS + m) * DD + h * DK + bn + c0];
            dst[0] = h0; dst[1] = h1;
        }
    }
}

// ======================= one merged fp32 -> fp16 convert =======================
__global__ __launch_bounds__(256) void k_f2hall(
    const float* __restrict__ q, const float* __restrict__ k, const float* __restrict__ v,
    const float* __restrict__ w0, const float* __restrict__ w1,
    const float* __restrict__ w2, const float* __restrict__ w3,
    __half* __restrict__ in16, __half* __restrict__ w16, int nW)
{
    int y = blockIdx.y;
    const float* x;
    __half* dst;
    if (y < 3) {
        x = (y == 0) ? q : (y == 1) ? k : v;
        dst = in16 + (size_t)y * MROWS * DD;
    } else {
        if (blockIdx.x >= (unsigned)nW) return;
        x = (y == 3) ? w0 : (y == 4) ? w1 : (y == 5) ? w2 : w3;
        dst = w16 + (size_t)(y - 3) * DD * DD;
    }
    size_t i = ((size_t)blockIdx.x * 256 + threadIdx.x) * 4;
    float4 val = *(const float4*)(x + i);
    *(__half2*)(dst + i)     = __floats2half2_rn(val.x, val.y);
    *(__half2*)(dst + i + 2) = __floats2half2_rn(val.z, val.w);
}

// ======================= warp-per-row softmax =======================
__global__ __launch_bounds__(256, 3) void k_softmax_w(float* __restrict__ P,
                                                      __half* __restrict__ P16)
{
    const size_t row = (size_t)blockIdx.x * 8 + (threadIdx.x >> 5);
    const int lane = threadIdx.x & 31;
    float4* p = (float4*)(P + row * SS);
    __half2* ph = (__half2*)(P16 + row * SS);

    float4 v[16];
#pragma unroll
    for (int i = 0; i < 16; i++) v[i] = p[lane + i * 32];

    float m = -INFINITY;
#pragma unroll
    for (int i = 0; i < 16; i++)
        m = fmaxf(m, fmaxf(fmaxf(v[i].x, v[i].y), fmaxf(v[i].z, v[i].w)));
#pragma unroll
    for (int o = 16; o; o >>= 1) m = fmaxf(m, __shfl_xor_sync(~0u, m, o));

    float s = 0.f;
#pragma unroll
    for (int i = 0; i < 16; i++) {
        v[i].x = __expf(v[i].x - m);
        v[i].y = __expf(v[i].y - m);
        v[i].z = __expf(v[i].z - m);
        v[i].w = __expf(v[i].w - m);
        s += (v[i].x + v[i].y) + (v[i].z + v[i].w);
    }
#pragma unroll
    for (int o = 16; o; o >>= 1) s += __shfl_xor_sync(~0u, s, o);
    float inv = 1.0f / s;

#pragma unroll
    for (int i = 0; i < 16; i++) {
        v[i].x *= inv; v[i].y *= inv; v[i].z *= inv; v[i].w *= inv;
        p[lane + i * 32] = v[i];
        ph[(lane + i * 32) * 2 + 0] = __floats2half2_rn(v[i].x, v[i].y);
        ph[(lane + i * 32) * 2 + 1] = __floats2half2_rn(v[i].z, v[i].w);
    }
}

// ======================= launch =======================
extern "C" void kernel_launch(void* const* d_in, const int* in_sizes, int n_in,
                              void* d_out, int out_size)
{
    const float* q    = (const float*)d_in[0];
    const float* k    = (const float*)d_in[1];
    const float* v    = (const float*)d_in[2];
    const int*   mask = (const int*)  d_in[3];
    const float* Wq   = (const float*)d_in[4];
    const float* bq_  = (const float*)d_in[5];
    const float* Wk   = (const float*)d_in[6];
    const float* bk_  = (const float*)d_in[7];
    const float* Wv   = (const float*)d_in[8];
    const float* bv_  = (const float*)d_in[9];
    const float* Wo   = (const float*)d_in[10];
    const float* bo_  = (const float*)d_in[11];
    float* out = (float*)d_out;

    const long long out_elems = (long long)MROWS * DD;
    const long long p_elems   = (long long)BB * HH * SS * SS;

    float* p_base;
    if ((long long)out_size >= out_elems + p_elems) {
        p_base = out + out_elems;
    } else {
        void* sp = nullptr;
        cudaGetSymbolAddress(&sp, g_pattn_scratch);
        p_base = (float*)sp;
    }

    void *pin16, *pa16, *pw16, *pqh, *pkh, *pvt, *pp16;
    cudaGetSymbolAddress(&pin16, g_in16);
    cudaGetSymbolAddress(&pa16, g_a16);
    cudaGetSymbolAddress(&pw16, g_w16);
    cudaGetSymbolAddress(&pqh,  g_qh16);
    cudaGetSymbolAddress(&pkh,  g_kh16);
    cudaGetSymbolAddress(&pvt,  g_vt16);
    cudaGetSymbolAddress(&pp16, g_p16);
    __half* in16 = (__half*)pin16;
    __half* a16 = (__half*)pa16;
    __half* w16 = (__half*)pw16;
    __half* qh16 = (__half*)pqh;
    __half* kh16 = (__half*)pkh;
    __half* vt16 = (__half*)pvt;
    __half* p16  = (__half*)pp16;

    const size_t inOff = (size_t)MROWS * DD;
    const size_t wOff  = (size_t)DD * DD;

    const int SM_PROJ = 82048;    // max(4*STG=81920, esm 128*133*4=68096) + align
    const int SM_SC   = 61568;    // 3*STG + align
    const int SM_AV   = 102528;   // 4*(256+64)*80 + align
    cudaFuncSetAttribute(tc_mm<2,4,4,4,4,0>, cudaFuncAttributeMaxDynamicSharedMemorySize, SM_PROJ);
    cudaFuncSetAttribute(tc_mm<2,4,4,4,4,7>, cudaFuncAttributeMaxDynamicSharedMemorySize, SM_PROJ);
    cudaFuncSetAttribute(tc_mm<2,4,4,4,3,3>, cudaFuncAttributeMaxDynamicSharedMemorySize, SM_SC);
    cudaFuncSetAttribute(tc_mm<4,2,4,4,4,4>, cudaFuncAttributeMaxDynamicSharedMemorySize, SM_AV);

    const int nIn = MROWS * DD / 1024;
    const int nW  = DD * DD / 1024;

    // all converts in one launch
    k_f2hall<<<dim3(nIn, 7), 256>>>(q, k, v, Wq, Wk, Wv, Wo, in16, w16, nW);

    // merged QKV projections: grid z = 0,1,2
    dim3 gProjQKV(DD / 128, MROWS / 128, 3);
    tc_mm<2,4,4,4,4,7><<<gProjQKV, 256, SM_PROJ>>>(in16, DD, inOff, w16, DD, wOff, DD,
        bq_, bk_, bv_, nullptr, nullptr, qh16, kh16, vt16);

    // scores (raw masked scaled) -> fp32 P, direct reg->gmem epilogue
    dim3 gScores(SS / 128, SS / 128, BB * HH);
    tc_mm<2,4,4,4,3,3><<<gScores, 256, SM_SC>>>(qh16, DK, (size_t)SS * DK,
        kh16, DK, (size_t)SS * DK, DK,
        nullptr, nullptr, nullptr, mask, p_base, nullptr, nullptr, nullptr);

    // warp-per-row softmax + fp16 copy
    k_softmax_w<<<BB * HH * SS / 8, 256>>>(p_base, p16);

    // AV: ctx = P16 @ Vt^T   (BM=256, BN=64, warp tile 64x32)
    dim3 gAV(1, SS / 256, BB * HH);
    tc_mm<4,2,4,4,4,4><<<gAV, 256, SM_AV>>>(p16, SS, (size_t)SS * SS,
        vt16, SS, (size_t)DK * SS, SS,
        nullptr, nullptr, nullptr, nullptr, nullptr, a16, nullptr, nullptr);

    // output projection: direct fp32 epilogue
    dim3 gProj(DD / 128, MROWS / 128, 1);
    tc_mm<2,4,4,4,4,0><<<gProj, 256, SM_PROJ>>>(a16, DD, 0, w16 + 3 * wOff, DD, 0, DD,
        bo_, nullptr, nullptr, nullptr, out, nullptr, nullptr, nullptr);
}